// round 2
// baseline (speedup 1.0000x reference)
#include <cuda_runtime.h>
#include <cstddef>

#define B_  32
#define N_  128
#define D_  512
#define H_  512
#define T_  31
#define TQ  32
#define G4  2048   // 4*H

// ---------------- device scratch (no allocations allowed) ----------------
__device__ float g_attn_feat[B_*N_*H_];   // [B*N, H]
__device__ float g_hop_feat [B_*N_*H_];
__device__ float g_wiht[D_*G4];           // packed: [k][j*4+g] = w_ih[g*H+j][k]
__device__ float g_whh [H_*G4];           // packed: [k][j*4+g] = w_hh[g*H+j][k]
__device__ float g_bias[G4];              // packed b_ih+b_hh
__device__ float g_X   [B_*TQ*D_];        // lstm input incl. init_i row
__device__ float g_xg  [B_*TQ*G4];        // X @ w_ih^T + bias (packed cols)
__device__ float g_hbuf[2][B_*H_];
__device__ float g_cbuf[B_*H_];
__device__ float g_query [B_*TQ*H_];
__device__ float g_qw    [B_*TQ*H_];
__device__ float g_score [B_*TQ*N_];
__device__ float g_query2[B_*TQ*H_];
__device__ float g_qw2   [B_*TQ*H_];

__device__ __forceinline__ float tanh_fast(float x) {
    float y; asm("tanh.approx.f32 %0, %1;" : "=f"(y) : "f"(x)); return y;
}
__device__ __forceinline__ float sigmoid_f(float x) {
    return 1.f / (1.f + __expf(-x));
}

// ---------------- weight pack / transpose ----------------
__global__ void pack_kernel(const float* __restrict__ w_ih, const float* __restrict__ w_hh,
                            const float* __restrict__ b_ih, const float* __restrict__ b_hh) {
    int idx = blockIdx.x * blockDim.x + threadIdx.x;
    if (idx < D_ * G4) {
        int k = idx >> 11, col = idx & 2047;
        int j = col >> 2, g = col & 3;
        int row = g * H_ + j;
        g_wiht[idx] = w_ih[row * D_ + k];
        g_whh [idx] = w_hh[row * H_ + k];
        if (idx < G4) g_bias[idx] = b_ih[row] + b_hh[row];
    }
}

__global__ void build_x_kernel(const float* __restrict__ lstm_in, const float* __restrict__ init_i) {
    int idx = blockIdx.x * blockDim.x + threadIdx.x;
    if (idx >= B_ * TQ * D_) return;
    int d  = idx & (D_ - 1);
    int bt = idx >> 9;
    int t = bt & 31, b = bt >> 5;
    g_X[idx] = (t == 0) ? init_i[d] : lstm_in[(b * T_ + (t - 1)) * D_ + d];
}

__global__ void init_hc_kernel(const float* __restrict__ init_h, const float* __restrict__ init_c) {
    int idx = blockIdx.x * blockDim.x + threadIdx.x;
    if (idx >= B_ * H_) return;
    int h = idx & (H_ - 1);
    g_hbuf[0][idx] = init_h[h];
    g_cbuf[idx]    = init_c[h];
}

// ---------------- tiled fp32 GEMM: C[M,N] = A[M,K] @ B[K,N] (+bias) ----------------
// BM=BN=64, BK=16, 256 threads, 4x4 microtile. All dims multiple of 64/16.
__global__ void sgemm64(const float* __restrict__ A, const float* __restrict__ Bm,
                        float* __restrict__ C, const float* __restrict__ bias,
                        int M, int N, int K) {
    __shared__ __align__(16) float As[16][64];   // [k][m]
    __shared__ __align__(16) float Bs[16][64];   // [k][n]
    const int bm = blockIdx.y * 64, bn = blockIdx.x * 64;
    const int tid = threadIdx.x;
    const int tn = tid & 15, tm = tid >> 4;
    const int arow = tid >> 2,  acol = (tid & 3) << 2;
    const int brow = tid >> 4,  bcol = (tid & 15) << 2;
    float acc[4][4] = {};
    for (int k0 = 0; k0 < K; k0 += 16) {
        float4 a4 = *(const float4*)(A  + (size_t)(bm + arow) * K + k0 + acol);
        float4 b4 = *(const float4*)(Bm + (size_t)(k0 + brow) * N + bn + bcol);
        As[acol + 0][arow] = a4.x;
        As[acol + 1][arow] = a4.y;
        As[acol + 2][arow] = a4.z;
        As[acol + 3][arow] = a4.w;
        *(float4*)&Bs[brow][bcol] = b4;
        __syncthreads();
#pragma unroll
        for (int k = 0; k < 16; k++) {
            float4 av = *(const float4*)&As[k][tm << 2];
            float4 bv = *(const float4*)&Bs[k][tn << 2];
            float a_[4] = {av.x, av.y, av.z, av.w};
            float b_[4] = {bv.x, bv.y, bv.z, bv.w};
#pragma unroll
            for (int i = 0; i < 4; i++)
#pragma unroll
                for (int j = 0; j < 4; j++) acc[i][j] += a_[i] * b_[j];
        }
        __syncthreads();
    }
#pragma unroll
    for (int i = 0; i < 4; i++) {
        int row = bm + (tm << 2) + i;
#pragma unroll
        for (int j = 0; j < 4; j++) {
            int col = bn + (tn << 2) + j;
            float v = acc[i][j];
            if (bias) v += bias[col];
            C[(size_t)row * N + col] = v;
        }
    }
}

// ---------------- LSTM step: g = xg[:,t,:] + h @ w_hh^T ; update h,c ----------------
// grid 128 = bhalf(2) x jslice(64 of 8 j); 256 threads = b_l(16) x jl(8) x khalf(2)
__global__ void lstm_step_kernel(int t) {
    int bx = blockIdx.x;
    int jslice = bx & 63, bhalf = bx >> 6;
    int tid = threadIdx.x;
    int b_l = tid >> 4;
    int rem = tid & 15;
    int jl = rem >> 1, kh = rem & 1;
    int b = bhalf * 16 + b_l;
    int j = jslice * 8 + jl;

    const float* hin  = g_hbuf[t & 1];
    float*       hout = g_hbuf[(t & 1) ^ 1];
    const float* hrow = hin + b * H_;
    const float* wp   = g_whh + j * 4;

    float acc0 = 0.f, acc1 = 0.f, acc2 = 0.f, acc3 = 0.f;
    int kbase = kh * 256;
#pragma unroll 4
    for (int k = kbase; k < kbase + 256; k += 4) {
        float4 h4 = *(const float4*)(hrow + k);
        float4 w0 = *(const float4*)(wp + (size_t)(k + 0) * G4);
        float4 w1 = *(const float4*)(wp + (size_t)(k + 1) * G4);
        float4 w2 = *(const float4*)(wp + (size_t)(k + 2) * G4);
        float4 w3 = *(const float4*)(wp + (size_t)(k + 3) * G4);
        acc0 += h4.x * w0.x; acc1 += h4.x * w0.y; acc2 += h4.x * w0.z; acc3 += h4.x * w0.w;
        acc0 += h4.y * w1.x; acc1 += h4.y * w1.y; acc2 += h4.y * w1.z; acc3 += h4.y * w1.w;
        acc0 += h4.z * w2.x; acc1 += h4.z * w2.y; acc2 += h4.z * w2.z; acc3 += h4.z * w2.w;
        acc0 += h4.w * w3.x; acc1 += h4.w * w3.y; acc2 += h4.w * w3.z; acc3 += h4.w * w3.w;
    }
    acc0 += __shfl_xor_sync(0xffffffffu, acc0, 1);
    acc1 += __shfl_xor_sync(0xffffffffu, acc1, 1);
    acc2 += __shfl_xor_sync(0xffffffffu, acc2, 1);
    acc3 += __shfl_xor_sync(0xffffffffu, acc3, 1);

    if (kh == 0) {
        int bt = b * TQ + t;
        const float* xg = g_xg + (size_t)bt * G4 + j * 4;
        float gi = acc0 + xg[0];
        float gf = acc1 + xg[1];
        float gg = acc2 + xg[2];
        float go = acc3 + xg[3];
        float c_ = sigmoid_f(gf) * g_cbuf[b * H_ + j] + sigmoid_f(gi) * tanhf(gg);
        float h_ = sigmoid_f(go) * tanhf(c_);
        g_cbuf[b * H_ + j] = c_;
        hout[b * H_ + j]   = h_;
        g_query[(size_t)bt * H_ + j] = h_;
    }
}

// ---------------- attention score: out[b,t,n] = sum_h tanh(feat[b,n,h]+qw[b,t,h])*v[h] ----------------
__global__ void score_kernel(const float* __restrict__ feat, const float* __restrict__ qw,
                             const float* __restrict__ v, float* __restrict__ out) {
    __shared__ __align__(16) float q_s[H_];
    __shared__ __align__(16) float v_s[H_];
    int bt = blockIdx.x;                 // 1024 blocks
    int b  = bt >> 5;
    int tid = threadIdx.x;               // 256
    q_s[tid]       = qw[(size_t)bt * H_ + tid];
    q_s[tid + 256] = qw[(size_t)bt * H_ + tid + 256];
    v_s[tid]       = v[tid];
    v_s[tid + 256] = v[tid + 256];
    __syncthreads();
    int warp = tid >> 5, lane = tid & 31;
    const float* fb = feat + (size_t)(b * N_) * H_;
    for (int n = warp; n < N_; n += 8) {
        const float* fr = fb + (size_t)n * H_;
        float acc = 0.f;
#pragma unroll
        for (int c = 0; c < 4; c++) {
            int h = c * 128 + lane * 4;
            float4 f4 = *(const float4*)(fr + h);
            float4 q4 = *(const float4*)(q_s + h);
            float4 v4 = *(const float4*)(v_s + h);
            acc += tanh_fast(f4.x + q4.x) * v4.x;
            acc += tanh_fast(f4.y + q4.y) * v4.y;
            acc += tanh_fast(f4.z + q4.z) * v4.z;
            acc += tanh_fast(f4.w + q4.w) * v4.w;
        }
#pragma unroll
        for (int s = 16; s; s >>= 1) acc += __shfl_xor_sync(0xffffffffu, acc, s);
        if (lane == 0) out[(size_t)bt * N_ + n] = acc;
    }
}

// ---------------- masked softmax over n + weighted sum: query2[b,t,:] = p @ hop_feat[b] ----------------
__global__ void softmax_wsum_kernel(const int* __restrict__ mem_sizes) {
    __shared__ float p_s[N_];
    __shared__ float red[128];
    int bt = blockIdx.x, b = bt >> 5;
    int tid = threadIdx.x;               // 128
    int ms = mem_sizes[b];
    float s = g_score[bt * N_ + tid];
    s = (tid < ms) ? s : -1e30f;
    red[tid] = s; __syncthreads();
    for (int o = 64; o; o >>= 1) { if (tid < o) red[tid] = fmaxf(red[tid], red[tid + o]); __syncthreads(); }
    float mx = red[0]; __syncthreads();
    float e = __expf(s - mx);
    red[tid] = e; __syncthreads();
    for (int o = 64; o; o >>= 1) { if (tid < o) red[tid] += red[tid + o]; __syncthreads(); }
    float inv = 1.f / red[0];
    p_s[tid] = e * inv;
    __syncthreads();
    const float* fb = g_hop_feat + (size_t)(b * N_) * H_;
    int h = tid * 4;
    float4 acc = {0.f, 0.f, 0.f, 0.f};
#pragma unroll 4
    for (int n = 0; n < N_; n++) {
        float p = p_s[n];
        float4 f = *(const float4*)(fb + (size_t)n * H_ + h);
        acc.x += p * f.x; acc.y += p * f.y; acc.z += p * f.z; acc.w += p * f.w;
    }
    *(float4*)&g_query2[(size_t)bt * H_ + h] = acc;
}

// ---------------- launch ----------------
static float* sym(const void* s) {
    void* p = nullptr;
    cudaGetSymbolAddress(&p, s);
    return (float*)p;
}

extern "C" void kernel_launch(void* const* d_in, const int* in_sizes, int n_in,
                              void* d_out, int out_size) {
    const float* attn_mem = (const float*)d_in[0];
    const int*   mem_sizes= (const int*)  d_in[1];
    const float* lstm_in  = (const float*)d_in[2];
    const float* init_h   = (const float*)d_in[3];
    const float* init_c   = (const float*)d_in[4];
    const float* init_i   = (const float*)d_in[5];
    const float* w_ih     = (const float*)d_in[6];
    const float* w_hh     = (const float*)d_in[7];
    const float* b_ih     = (const float*)d_in[8];
    const float* b_hh     = (const float*)d_in[9];
    const float* attn_wm  = (const float*)d_in[10];
    const float* attn_wq  = (const float*)d_in[11];
    const float* attn_v   = (const float*)d_in[12];
    const float* hop_wm   = (const float*)d_in[13];
    const float* hop_wq   = (const float*)d_in[14];
    const float* hop_v    = (const float*)d_in[15];
    float* out = (float*)d_out;

    float* p_attn_feat = sym(g_attn_feat);
    float* p_hop_feat  = sym(g_hop_feat);
    float* p_wiht      = sym(g_wiht);
    float* p_bias      = sym(g_bias);
    float* p_X         = sym(g_X);
    float* p_xg        = sym(g_xg);
    float* p_query     = sym(g_query);
    float* p_qw        = sym(g_qw);
    float* p_score     = sym(g_score);
    float* p_query2    = sym(g_query2);
    float* p_qw2       = sym(g_qw2);
    (void)p_wiht;

    // prep
    pack_kernel   <<<(D_*G4 + 255)/256, 256>>>(w_ih, w_hh, b_ih, b_hh);
    build_x_kernel<<<(B_*TQ*D_ + 255)/256, 256>>>(lstm_in, init_i);
    init_hc_kernel<<<(B_*H_ + 255)/256, 256>>>(init_h, init_c);

    // feature GEMMs: [4096,512] @ [512,512]
    sgemm64<<<dim3(H_/64, (B_*N_)/64), 256>>>(attn_mem, attn_wm, p_attn_feat, nullptr, B_*N_, H_, D_);
    sgemm64<<<dim3(H_/64, (B_*N_)/64), 256>>>(attn_mem, hop_wm,  p_hop_feat,  nullptr, B_*N_, H_, D_);

    // input gates: [1024,512] @ [512,2048] + bias
    sgemm64<<<dim3(G4/64, (B_*TQ)/64), 256>>>(p_X, sym(g_wiht), p_xg, p_bias, B_*TQ, G4, D_);

    // LSTM recurrence (one node per step; stream order = inter-step sync)
    for (int t = 0; t < TQ; t++)
        lstm_step_kernel<<<128, 256>>>(t);

    // hop attention
    sgemm64<<<dim3(H_/64, (B_*TQ)/64), 256>>>(p_query, hop_wq, p_qw, nullptr, B_*TQ, H_, H_);
    score_kernel<<<B_*TQ, 256>>>(p_hop_feat, p_qw, hop_v, p_score);
    softmax_wsum_kernel<<<B_*TQ, 128>>>(mem_sizes);

    // final score
    sgemm64<<<dim3(H_/64, (B_*TQ)/64), 256>>>(p_query2, attn_wq, p_qw2, nullptr, B_*TQ, H_, H_);
    score_kernel<<<B_*TQ, 256>>>(p_attn_feat, p_qw2, attn_v, out);
}

// round 3
// speedup vs baseline: 2.2978x; 2.2978x over previous
#include <cuda_runtime.h>
#include <cstddef>

#define B_  32
#define N_  128
#define D_  512
#define H_  512
#define T_  31
#define TQ  32
#define G4  2048   // 4*H
#define FEATW 1024 // attn|hop feature cols

// ---------------- device scratch (no allocations allowed) ----------------
__device__ float g_feat [B_*N_*FEATW];    // [B*N][1024]: cols 0..511 attn, 512..1023 hop
__device__ float g_wfeat[D_*FEATW];       // [k][1024] = attn_wm | hop_wm
__device__ float g_wiht[D_*G4];           // packed: [k][j*4+g] = w_ih[g*H+j][k]
__device__ float g_whh [H_*G4];           // packed: [k][j*4+g] = w_hh[g*H+j][k]
__device__ float g_bias[G4];              // packed b_ih+b_hh
__device__ float g_X   [B_*TQ*D_];        // lstm input incl. init_i row
__device__ float g_xg  [B_*TQ*G4];        // X @ w_ih^T + bias (packed cols)
__device__ float g_hT  [2][H_*B_];        // transposed h state: [k][b], double-buffered
__device__ float g_cbuf[B_*H_];
__device__ float g_query [B_*TQ*H_];
__device__ float g_qw    [B_*TQ*H_];
__device__ float g_score [B_*TQ*N_];
__device__ float g_query2[B_*TQ*H_];
__device__ float g_qw2   [B_*TQ*H_];

__device__ __forceinline__ float tanh_fast(float x) {
    float y; asm("tanh.approx.f32 %0, %1;" : "=f"(y) : "f"(x)); return y;
}
__device__ __forceinline__ float sigmoid_f(float x) {
    return 1.f / (1.f + __expf(-x));
}

// ---------------- weight pack / transpose ----------------
__global__ void pack_kernel(const float* __restrict__ w_ih, const float* __restrict__ w_hh,
                            const float* __restrict__ b_ih, const float* __restrict__ b_hh,
                            const float* __restrict__ attn_wm, const float* __restrict__ hop_wm) {
    int idx = blockIdx.x * blockDim.x + threadIdx.x;
    if (idx < D_ * G4) {
        int k = idx >> 11, col = idx & 2047;
        int j = col >> 2, g = col & 3;
        int row = g * H_ + j;
        g_wiht[idx] = w_ih[row * D_ + k];
        g_whh [idx] = w_hh[row * H_ + k];
        if (idx < G4) g_bias[idx] = b_ih[row] + b_hh[row];
    }
    if (idx < D_ * FEATW) {
        int k = idx >> 10, c = idx & 1023;
        g_wfeat[idx] = (c < 512) ? attn_wm[k * H_ + c] : hop_wm[k * H_ + (c - 512)];
    }
}

__global__ void build_x_kernel(const float* __restrict__ lstm_in, const float* __restrict__ init_i) {
    int idx = blockIdx.x * blockDim.x + threadIdx.x;
    if (idx >= B_ * TQ * D_) return;
    int d  = idx & (D_ - 1);
    int bt = idx >> 9;
    int t = bt & 31, b = bt >> 5;
    g_X[idx] = (t == 0) ? init_i[d] : lstm_in[(b * T_ + (t - 1)) * D_ + d];
}

__global__ void init_hc_kernel(const float* __restrict__ init_h, const float* __restrict__ init_c) {
    int idx = blockIdx.x * blockDim.x + threadIdx.x;
    if (idx >= B_ * H_) return;
    int b = idx & 31, j = idx >> 5;       // idx = j*32 + b
    g_hT[0][idx] = init_h[j];
    g_cbuf[b * H_ + j] = init_c[j];
}

// ---------------- tiled fp32 GEMM: C[M,N] = A[M,K] @ B[K,N] (+bias) ----------------
__global__ void sgemm64(const float* __restrict__ A, const float* __restrict__ Bm,
                        float* __restrict__ C, const float* __restrict__ bias,
                        int M, int N, int K) {
    __shared__ __align__(16) float As[16][64];   // [k][m]
    __shared__ __align__(16) float Bs[16][64];   // [k][n]
    const int bm = blockIdx.y * 64, bn = blockIdx.x * 64;
    const int tid = threadIdx.x;
    const int tn = tid & 15, tm = tid >> 4;
    const int arow = tid >> 2,  acol = (tid & 3) << 2;
    const int brow = tid >> 4,  bcol = (tid & 15) << 2;
    float acc[4][4] = {};
    for (int k0 = 0; k0 < K; k0 += 16) {
        float4 a4 = *(const float4*)(A  + (size_t)(bm + arow) * K + k0 + acol);
        float4 b4 = *(const float4*)(Bm + (size_t)(k0 + brow) * N + bn + bcol);
        As[acol + 0][arow] = a4.x;
        As[acol + 1][arow] = a4.y;
        As[acol + 2][arow] = a4.z;
        As[acol + 3][arow] = a4.w;
        *(float4*)&Bs[brow][bcol] = b4;
        __syncthreads();
#pragma unroll
        for (int k = 0; k < 16; k++) {
            float4 av = *(const float4*)&As[k][tm << 2];
            float4 bv = *(const float4*)&Bs[k][tn << 2];
            float a_[4] = {av.x, av.y, av.z, av.w};
            float b_[4] = {bv.x, bv.y, bv.z, bv.w};
#pragma unroll
            for (int i = 0; i < 4; i++)
#pragma unroll
                for (int j = 0; j < 4; j++) acc[i][j] += a_[i] * b_[j];
        }
        __syncthreads();
    }
#pragma unroll
    for (int i = 0; i < 4; i++) {
        int row = bm + (tm << 2) + i;
#pragma unroll
        for (int j = 0; j < 4; j++) {
            int col = bn + (tn << 2) + j;
            float v = acc[i][j];
            if (bias) v += bias[col];
            C[(size_t)row * N + col] = v;
        }
    }
}

// ---------------- LSTM step ----------------
// G[32b x 16col] = hT^T @ W per block; 128 blocks (16 packed gate-cols each).
// 256 thr = 8 k-seg warps x (8 b-quads x 4 c-quads), 4x4 microtile over 64 k.
// hT[k][b] layout => one 128B line per k per warp. Partials reduced via smem.
__global__ void __launch_bounds__(256, 1) lstm_step_kernel(int t) {
    __shared__ float red[8][32 * 17 + 1];   // [ks][b*17 + c]
    const int bid = blockIdx.x;             // col block: cols [bid*16, bid*16+16)
    const int tid = threadIdx.x;
    const int ks = tid >> 5, lane = tid & 31;
    const int bq = lane & 7, cq = lane >> 3;

    const float* __restrict__ hT = g_hT[t & 1];
    const float* __restrict__ hp = hT + (ks << 6) * B_ + (bq << 2);
    const float* __restrict__ wp = g_whh + (size_t)(ks << 6) * G4 + bid * 16 + (cq << 2);

    float acc[4][4] = {};
#pragma unroll 8
    for (int k = 0; k < 64; k++) {
        float4 h4 = *(const float4*)(hp + k * B_);
        float4 w4 = *(const float4*)(wp + (size_t)k * G4);
        float h_[4] = {h4.x, h4.y, h4.z, h4.w};
        float w_[4] = {w4.x, w4.y, w4.z, w4.w};
#pragma unroll
        for (int i = 0; i < 4; i++)
#pragma unroll
            for (int j = 0; j < 4; j++) acc[i][j] += h_[i] * w_[j];
    }
#pragma unroll
    for (int i = 0; i < 4; i++)
#pragma unroll
        for (int j = 0; j < 4; j++)
            red[ks][((bq << 2) + i) * 17 + (cq << 2) + j] = acc[i][j];
    __syncthreads();

    if (tid < 128) {
        int b = tid >> 2, jl = tid & 3;
        int j = (bid << 2) + jl;
        int bt = b * TQ + t;
        const float* xg = g_xg + (size_t)bt * G4 + bid * 16 + (jl << 2);
        float gate[4];
#pragma unroll
        for (int g = 0; g < 4; g++) {
            int c = (jl << 2) + g;
            float s = 0.f;
#pragma unroll
            for (int kk = 0; kk < 8; kk++) s += red[kk][b * 17 + c];
            gate[g] = s + xg[g];
        }
        float c_ = sigmoid_f(gate[1]) * g_cbuf[b * H_ + j] + sigmoid_f(gate[0]) * tanhf(gate[2]);
        float h_ = sigmoid_f(gate[3]) * tanhf(c_);
        g_cbuf[b * H_ + j] = c_;
        g_hT[(t & 1) ^ 1][j * B_ + b] = h_;
        g_query[(size_t)bt * H_ + j] = h_;
    }
}

// ---------------- attention score ----------------
// out[b,t,n] = sum_h tanh(feat[b,n,h]+qw[b,t,h])*v[h]; feat row stride ST.
__global__ void score_kernel(const float* __restrict__ feat, int ST,
                             const float* __restrict__ qw,
                             const float* __restrict__ v, float* __restrict__ out) {
    __shared__ __align__(16) float q_s[H_];
    __shared__ __align__(16) float v_s[H_];
    int bt = blockIdx.x;                 // 1024 blocks
    int b  = bt >> 5;
    int tid = threadIdx.x;               // 256
    q_s[tid]       = qw[(size_t)bt * H_ + tid];
    q_s[tid + 256] = qw[(size_t)bt * H_ + tid + 256];
    v_s[tid]       = v[tid];
    v_s[tid + 256] = v[tid + 256];
    __syncthreads();
    int warp = tid >> 5, lane = tid & 31;
    const float* fb = feat + (size_t)(b * N_) * ST;
    for (int n = warp; n < N_; n += 8) {
        const float* fr = fb + (size_t)n * ST;
        float acc = 0.f;
#pragma unroll
        for (int c = 0; c < 4; c++) {
            int h = c * 128 + lane * 4;
            float4 f4 = *(const float4*)(fr + h);
            float4 q4 = *(const float4*)(q_s + h);
            float4 v4 = *(const float4*)(v_s + h);
            acc += tanh_fast(f4.x + q4.x) * v4.x;
            acc += tanh_fast(f4.y + q4.y) * v4.y;
            acc += tanh_fast(f4.z + q4.z) * v4.z;
            acc += tanh_fast(f4.w + q4.w) * v4.w;
        }
#pragma unroll
        for (int s = 16; s; s >>= 1) acc += __shfl_xor_sync(0xffffffffu, acc, s);
        if (lane == 0) out[(size_t)bt * N_ + n] = acc;
    }
}

// ---------------- masked softmax + weighted sum over hop_feat ----------------
__global__ void softmax_wsum_kernel(const int* __restrict__ mem_sizes,
                                    const float* __restrict__ hopfeat, int ST) {
    __shared__ float p_s[N_];
    __shared__ float red[128];
    int bt = blockIdx.x, b = bt >> 5;
    int tid = threadIdx.x;               // 128
    int ms = mem_sizes[b];
    float s = g_score[bt * N_ + tid];
    s = (tid < ms) ? s : -1e30f;
    red[tid] = s; __syncthreads();
    for (int o = 64; o; o >>= 1) { if (tid < o) red[tid] = fmaxf(red[tid], red[tid + o]); __syncthreads(); }
    float mx = red[0]; __syncthreads();
    float e = __expf(s - mx);
    red[tid] = e; __syncthreads();
    for (int o = 64; o; o >>= 1) { if (tid < o) red[tid] += red[tid + o]; __syncthreads(); }
    float inv = 1.f / red[0];
    p_s[tid] = e * inv;
    __syncthreads();
    const float* fb = hopfeat + (size_t)(b * N_) * ST;
    int h = tid * 4;
    float4 acc = {0.f, 0.f, 0.f, 0.f};
#pragma unroll 4
    for (int n = 0; n < N_; n++) {
        float p = p_s[n];
        float4 f = *(const float4*)(fb + (size_t)n * ST + h);
        acc.x += p * f.x; acc.y += p * f.y; acc.z += p * f.z; acc.w += p * f.w;
    }
    *(float4*)&g_query2[(size_t)bt * H_ + h] = acc;
}

// ---------------- launch ----------------
static float* sym(const void* s) {
    void* p = nullptr;
    cudaGetSymbolAddress(&p, s);
    return (float*)p;
}

extern "C" void kernel_launch(void* const* d_in, const int* in_sizes, int n_in,
                              void* d_out, int out_size) {
    const float* attn_mem = (const float*)d_in[0];
    const int*   mem_sizes= (const int*)  d_in[1];
    const float* lstm_in  = (const float*)d_in[2];
    const float* init_h   = (const float*)d_in[3];
    const float* init_c   = (const float*)d_in[4];
    const float* init_i   = (const float*)d_in[5];
    const float* w_ih     = (const float*)d_in[6];
    const float* w_hh     = (const float*)d_in[7];
    const float* b_ih     = (const float*)d_in[8];
    const float* b_hh     = (const float*)d_in[9];
    const float* attn_wm  = (const float*)d_in[10];
    const float* attn_wq  = (const float*)d_in[11];
    const float* attn_v   = (const float*)d_in[12];
    const float* hop_wm   = (const float*)d_in[13];
    const float* hop_wq   = (const float*)d_in[14];
    const float* hop_v    = (const float*)d_in[15];
    float* out = (float*)d_out;

    float* p_feat   = sym(g_feat);
    float* p_wfeat  = sym(g_wfeat);
    float* p_wiht   = sym(g_wiht);
    float* p_bias   = sym(g_bias);
    float* p_X      = sym(g_X);
    float* p_xg     = sym(g_xg);
    float* p_query  = sym(g_query);
    float* p_qw     = sym(g_qw);
    float* p_score  = sym(g_score);
    float* p_query2 = sym(g_query2);
    float* p_qw2    = sym(g_qw2);

    // prep
    pack_kernel   <<<(D_*G4 + 255)/256, 256>>>(w_ih, w_hh, b_ih, b_hh, attn_wm, hop_wm);
    build_x_kernel<<<(B_*TQ*D_ + 255)/256, 256>>>(lstm_in, init_i);
    init_hc_kernel<<<(B_*H_ + 255)/256, 256>>>(init_h, init_c);

    // merged feature GEMM: [4096,512] @ [512,1024] -> g_feat (attn|hop)
    sgemm64<<<dim3(FEATW/64, (B_*N_)/64), 256>>>(attn_mem, p_wfeat, p_feat, nullptr, B_*N_, FEATW, D_);

    // input gates: [1024,512] @ [512,2048] + bias
    sgemm64<<<dim3(G4/64, (B_*TQ)/64), 256>>>(p_X, p_wiht, p_xg, p_bias, B_*TQ, G4, D_);

    // LSTM recurrence (one node per step)
    for (int t = 0; t < TQ; t++)
        lstm_step_kernel<<<128, 256>>>(t);

    // hop attention (hop feat = cols 512..1023 of g_feat)
    sgemm64<<<dim3(H_/64, (B_*TQ)/64), 256>>>(p_query, hop_wq, p_qw, nullptr, B_*TQ, H_, H_);
    score_kernel<<<B_*TQ, 256>>>(p_feat + 512, FEATW, p_qw, hop_v, p_score);
    softmax_wsum_kernel<<<B_*TQ, 128>>>(mem_sizes, p_feat + 512, FEATW);

    // final score (attn feat = cols 0..511)
    sgemm64<<<dim3(H_/64, (B_*TQ)/64), 256>>>(p_query2, attn_wq, p_qw2, nullptr, B_*TQ, H_, H_);
    score_kernel<<<B_*TQ, 256>>>(p_feat, FEATW, p_qw2, attn_v, out);
}